// round 2
// baseline (speedup 1.0000x reference)
#include <cuda_runtime.h>
#include <cstdint>

#define NL 50
#define ND 64
#define NROWS 50000
#define TOTROWS 100000
#define SSTRIDE 52

// 1 / sum_{m=0}^{49} e^{-m}
#define INV_C 0.63212055882855767841f

__device__ float g_S[(size_t)TOTROWS * SSTRIDE];   // te-dot scratch
__device__ float g_H[(size_t)TOTROWS * ND];        // attention output scratch

#define CPASYNC16(smem_u32, gptr) \
    asm volatile("cp.async.cg.shared.global [%0], [%1], 16;\n" :: "r"(smem_u32), "l"(gptr))

// ------------------------------------------------------------------
// Kernel 0: S[row][k] = <dst_h[row], te[k]>, two threads per row.
// ------------------------------------------------------------------
__global__ __launch_bounds__(128) void te_dot_kernel(
    const float* __restrict__ user_h, const float* __restrict__ item_h,
    const float* __restrict__ u_te,   const float* __restrict__ i_te)
{
    __shared__ __align__(16) float4 s_te[NL * 16];
    const int side = blockIdx.y;
    const float* hsrc = side == 0 ? user_h : item_h;
    const float* te   = side == 0 ? u_te   : i_te;

    for (int i = threadIdx.x; i < NL * 16; i += 128)
        s_te[i] = ((const float4*)te)[i];
    __syncthreads();

    const int half = threadIdx.x & 1;
    int n = blockIdx.x * 64 + (threadIdx.x >> 1);
    const bool valid = n < NROWS;
    if (!valid) n = 0;

    float4 h4[8];
    const float4* hrow = (const float4*)(hsrc + (size_t)n * ND) + half * 8;
#pragma unroll
    for (int c = 0; c < 8; c++) h4[c] = hrow[c];

    float* Srow = g_S + ((size_t)side * NROWS + n) * SSTRIDE;
#pragma unroll 2
    for (int k = 0; k < NL; k++) {
        float acc = 0.f;
#pragma unroll
        for (int c = 0; c < 8; c++) {
            float4 t4 = s_te[k * 16 + half * 8 + c];
            acc += h4[c].x * t4.x + h4[c].y * t4.y + h4[c].z * t4.z + h4[c].w * t4.w;
        }
        acc += __shfl_xor_sync(0xffffffffu, acc, 1);
        if (valid && ((k & 1) == half)) Srow[k] = acc;
    }
}

// ------------------------------------------------------------------
// Kernel 1: per-row attention. 64 threads per row. XOR-swizzled 50x64 tile,
// cp.async gather overlapped with rank computation.
// Swizzle: logical float4 chunk c of row l stored at physical chunk c^(l&15).
// ------------------------------------------------------------------
__global__ __launch_bounds__(64) void attn_kernel(
    const float* __restrict__ user_h, const float* __restrict__ item_h,
    const int* __restrict__ u_nbr, const int* __restrict__ u_tim,
    const int* __restrict__ i_nbr, const int* __restrict__ i_tim)
{
    __shared__ __align__(16) float s_nbr[NL * 64];   // 12.8 KB swizzled tile
    __shared__ __align__(16) float s_dst[ND];
    __shared__ __align__(16) int   s_tim[52];
    __shared__ __align__(16) int   s_srt[52];
    __shared__ __align__(16) float s_S[52];
    __shared__ __align__(16) float s_g[52];
    __shared__ __align__(16) float s_alpha[52];

    const int row = blockIdx.x;
    const int t = threadIdx.x;
    const bool uside = row < NROWS;
    const int n = uside ? row : row - NROWS;
    const float* dst = (uside ? user_h : item_h) + (size_t)n * ND;
    const float* src = uside ? item_h : user_h;
    const int* nbr = (uside ? u_nbr : i_nbr) + (size_t)n * NL;
    const int* tim = (uside ? u_tim : i_tim) + (size_t)n * NL;
    const float* Srow = g_S + (size_t)row * SSTRIDE;

    int r_idx = 0, r_tim = 0;
    float r_S = 0.f;
    if (t < NL) {
        r_idx = __ldg(nbr + t);
        r_tim = __ldg(tim + t);
        r_S   = __ldg(Srow + t);
    }
    s_dst[t] = __ldg(dst + t);
    if (t < NL) {
        s_tim[t] = r_tim;
        s_S[t]   = r_S;
    } else if (t < 52) {
        s_tim[t]   = 0x7fffffff;
        s_g[t]     = -1e30f;
        s_alpha[t] = 0.f;
    }

    // --- gather: thread l fetches its whole neighbor row via cp.async ---
    if (t < NL) {
        const char* srow = (const char*)(src + (size_t)r_idx * ND);
        unsigned sbase = (unsigned)__cvta_generic_to_shared(&s_nbr[t * 64]);
        const int sw = (t & 15) << 4;
#pragma unroll
        for (int c = 0; c < 16; c++)
            CPASYNC16(sbase + ((c << 4) ^ sw), srow + c * 16);
    }
    asm volatile("cp.async.commit_group;\n");
    __syncthreads();   // s_tim visible

    // --- rank / srt while gather is in flight ---
    int ro = 0;
    if (t < NL) {
        const int tl = s_tim[t];
        int r = 0;
#pragma unroll
        for (int i = 0; i < 13; i++) {
            int4 v = ((const int4*)s_tim)[i];
            int j = 4 * i;
            r += (v.x < tl) | ((v.x == tl) & (j     < t));
            r += (v.y < tl) | ((v.y == tl) & (j + 1 < t));
            r += (v.z < tl) | ((v.z == tl) & (j + 2 < t));
            r += (v.w < tl) | ((v.w == tl) & (j + 3 < t));
        }
        s_srt[r] = t;
        ro = NL - 1 - r;
    }
    asm volatile("cp.async.wait_all;\n");
    __syncthreads();   // tile + s_srt visible

    // --- scores: e[l] = (<nbr_l,dst> + S[ro_l]) * 6.25; g = e * p ---
    if (t < NL) {
        const float4* rowp = (const float4*)&s_nbr[t * 64];
        const float4* d4 = (const float4*)s_dst;
        const int sw4 = t & 15;
        float acc = 0.f;
#pragma unroll
        for (int c = 0; c < 16; c++) {
            float4 a = rowp[c];            // physical chunk c = logical c^sw4
            float4 b = d4[c ^ sw4];
            acc += a.x * b.x + a.y * b.y + a.z * b.z + a.w * b.w;
        }
        float e = (acc + s_S[ro]) * 6.25f;                 // L/sqrt(D)
        float p = expf((float)s_srt[t] - 49.0f) * INV_C;
        s_g[t] = e * p;
    }
    __syncthreads();

    // --- softmax (redundant per-thread from smem) ---
    float m = -1e30f;
#pragma unroll
    for (int i = 0; i < 13; i++) {
        float4 g4 = ((const float4*)s_g)[i];
        m = fmaxf(m, fmaxf(fmaxf(g4.x, g4.y), fmaxf(g4.z, g4.w)));
    }
    if (t < NL) s_alpha[t] = expf(s_g[t] - m);
    __syncthreads();
    float sum = 0.f;
#pragma unroll
    for (int i = 0; i < 13; i++) {
        float4 a4 = ((const float4*)s_alpha)[i];
        sum += a4.x + a4.y + a4.z + a4.w;
    }
    const float inv = 1.0f / sum;

    // --- weighted sum: h[t] = sum_l alpha[l] * nbr[l][t] ---
    const int g = t >> 2, r4 = t & 3;
    float h = 0.f;
#pragma unroll
    for (int i = 0; i < 12; i++) {
        float4 a4 = ((const float4*)s_alpha)[i];
        int l = 4 * i;
        h += a4.x * s_nbr[(l    ) * 64 + (((g ^ ((l    ) & 15)) << 2) | r4)];
        h += a4.y * s_nbr[(l + 1) * 64 + (((g ^ ((l + 1) & 15)) << 2) | r4)];
        h += a4.z * s_nbr[(l + 2) * 64 + (((g ^ ((l + 2) & 15)) << 2) | r4)];
        h += a4.w * s_nbr[(l + 3) * 64 + (((g ^ ((l + 3) & 15)) << 2) | r4)];
    }
    h += s_alpha[48] * s_nbr[48 * 64 + (((g ^ 0) << 2) | r4)];
    h += s_alpha[49] * s_nbr[49 * 64 + (((g ^ 1) << 2) | r4)];

    g_H[(size_t)row * ND + t] = h * inv;
}

// ------------------------------------------------------------------
// Kernel 2: out = relu(H @ W1 + b1) @ W2 + b2; 2 rows per thread.
// ------------------------------------------------------------------
__global__ __launch_bounds__(128) void mlp_kernel(
    const float* __restrict__ W1u, const float* __restrict__ b1u,
    const float* __restrict__ W2u, const float* __restrict__ b2u,
    const float* __restrict__ W1i, const float* __restrict__ b1i,
    const float* __restrict__ W2i, const float* __restrict__ b2i,
    float* __restrict__ out)
{
    __shared__ __align__(16) float4 sW1[ND * 16];
    __shared__ __align__(16) float4 sW2[ND * 16];
    __shared__ __align__(16) float4 sb1[16];
    __shared__ __align__(16) float4 sb2[16];

    const int side = blockIdx.y;
    const float* W1 = side ? W1i : W1u;
    const float* W2 = side ? W2i : W2u;
    const float* b1 = side ? b1i : b1u;
    const float* b2 = side ? b2i : b2u;

    for (int i = threadIdx.x; i < ND * 16; i += 128) {
        sW1[i] = ((const float4*)W1)[i];
        sW2[i] = ((const float4*)W2)[i];
    }
    if (threadIdx.x < 16) {
        sb1[threadIdx.x] = ((const float4*)b1)[threadIdx.x];
        sb2[threadIdx.x] = ((const float4*)b2)[threadIdx.x];
    }
    __syncthreads();

    for (int j = 0; j < 2; j++) {
        const int n = blockIdx.x * 256 + j * 128 + threadIdx.x;
        if (n >= NROWS) continue;
        const size_t grow = (size_t)side * NROWS + n;

        float hreg[ND];
        const float4* Hrow = (const float4*)(g_H + grow * ND);
#pragma unroll
        for (int c = 0; c < 16; c++) ((float4*)hreg)[c] = Hrow[c];

        float4 o1[16];
#pragma unroll
        for (int c = 0; c < 16; c++) o1[c] = sb1[c];
#pragma unroll
        for (int k = 0; k < ND; k++) {
            float hk = hreg[k];
#pragma unroll
            for (int c = 0; c < 16; c++) {
                float4 w = sW1[k * 16 + c];
                o1[c].x += hk * w.x; o1[c].y += hk * w.y;
                o1[c].z += hk * w.z; o1[c].w += hk * w.w;
            }
        }
        float o1f[ND];
#pragma unroll
        for (int c = 0; c < 16; c++) {
            o1f[4 * c + 0] = fmaxf(o1[c].x, 0.f);
            o1f[4 * c + 1] = fmaxf(o1[c].y, 0.f);
            o1f[4 * c + 2] = fmaxf(o1[c].z, 0.f);
            o1f[4 * c + 3] = fmaxf(o1[c].w, 0.f);
        }

        float4 o2[16];
#pragma unroll
        for (int c = 0; c < 16; c++) o2[c] = sb2[c];
#pragma unroll
        for (int k = 0; k < ND; k++) {
            float hk = o1f[k];
#pragma unroll
            for (int c = 0; c < 16; c++) {
                float4 w = sW2[k * 16 + c];
                o2[c].x += hk * w.x; o2[c].y += hk * w.y;
                o2[c].z += hk * w.z; o2[c].w += hk * w.w;
            }
        }

        float4* orow = (float4*)(out + grow * ND);
#pragma unroll
        for (int c = 0; c < 16; c++) orow[c] = o2[c];
    }
}

// ------------------------------------------------------------------
extern "C" void kernel_launch(void* const* d_in, const int* in_sizes, int n_in,
                              void* d_out, int out_size)
{
    const float* user_h = (const float*)d_in[0];
    const float* item_h = (const float*)d_in[1];
    const float* u_te   = (const float*)d_in[2];
    const float* i_te   = (const float*)d_in[3];
    const float* Wu1 = (const float*)d_in[4];
    const float* bu1 = (const float*)d_in[5];
    const float* Wu2 = (const float*)d_in[6];
    const float* bu2 = (const float*)d_in[7];
    const float* Wi1 = (const float*)d_in[8];
    const float* bi1 = (const float*)d_in[9];
    const float* Wi2 = (const float*)d_in[10];
    const float* bi2 = (const float*)d_in[11];
    const int* u_nbr = (const int*)d_in[12];
    const int* u_tim = (const int*)d_in[13];
    const int* i_nbr = (const int*)d_in[14];
    const int* i_tim = (const int*)d_in[15];
    float* out = (float*)d_out;

    te_dot_kernel<<<dim3((NROWS + 63) / 64, 2), 128>>>(user_h, item_h, u_te, i_te);
    attn_kernel<<<TOTROWS, 64>>>(user_h, item_h, u_nbr, u_tim, i_nbr, i_tim);
    mlp_kernel<<<dim3((NROWS + 255) / 256, 2), 128>>>(Wu1, bu1, Wu2, bu2,
                                                      Wi1, bi1, Wi2, bi2, out);
}

// round 3
// speedup vs baseline: 1.9742x; 1.9742x over previous
#include <cuda_runtime.h>
#include <cstdint>

#define NL 50
#define ND 64
#define NROWS 50000
#define TOTROWS 100000

// 1 / sum_{m=0}^{49} e^{-m}
#define INV_C 0.63212055882855767841f

__device__ float g_H[(size_t)TOTROWS * ND];   // attention output scratch (25.6 MB)

// ------------------------------------------------------------------
// Fused attention kernel: one 64-thread block per destination row.
// Neighbor tile lives in REGISTERS (13 float4/thread); score dots and
// te dots are shfl-reduced over 16-lane groups; no big smem tile.
// Thread t: group g = t>>4 (rows 4i+g), chunk c = t&15 (columns 4c..4c+3).
// ------------------------------------------------------------------
__global__ __launch_bounds__(64) void attn_kernel(
    const float* __restrict__ user_h, const float* __restrict__ item_h,
    const float* __restrict__ u_te,   const float* __restrict__ i_te,
    const int* __restrict__ u_nbr, const int* __restrict__ u_tim,
    const int* __restrict__ i_nbr, const int* __restrict__ i_tim)
{
    __shared__ __align__(16) int   s_tim[52];
    __shared__ __align__(16) int   s_idx[52];
    __shared__ __align__(16) int   s_srt[52];
    __shared__ __align__(16) float s_dot[52];
    __shared__ __align__(16) float s_S[52];
    __shared__ __align__(16) float s_g[52];
    __shared__ __align__(16) float s_alpha[52];
    __shared__ __align__(16) float4 s_red[32];    // [warp][chunk]

    const int row = blockIdx.x;
    const int t = threadIdx.x;
    const int g = t >> 4, c = t & 15;
    const bool uside = row < NROWS;
    const int n = uside ? row : row - NROWS;
    const float*  dst  = (uside ? user_h : item_h) + (size_t)n * ND;
    const float4* src4 = (const float4*)(uside ? item_h : user_h);
    const float4* te4  = (const float4*)(uside ? u_te : i_te);
    const int* nbr = (uside ? u_nbr : i_nbr) + (size_t)n * NL;
    const int* tim = (uside ? u_tim : i_tim) + (size_t)n * NL;

    const float4 dstc = __ldg(&((const float4*)dst)[c]);   // my dst chunk

    if (t < NL) {
        s_idx[t] = __ldg(nbr + t);
        s_tim[t] = __ldg(tim + t);
    } else if (t < 52) {
        s_tim[t]   = 0x7fffffff;   // pad: strictly greater, no ties with j<t rule
        s_idx[t]   = 0;
        s_g[t]     = -1e30f;       // pad for max loop
        s_alpha[t] = 0.f;          // pad for sum / pass-C
    }
    __syncthreads();

    // --- gather: 16 consecutive lanes fetch one 256B neighbor row (coalesced) ---
    float4 v[13];
#pragma unroll
    for (int i = 0; i < 13; i++) {
        const int l = 4 * i + g;
        if (l < NL)
            v[i] = __ldg(&src4[(size_t)s_idx[l] * 16 + c]);
        else
            v[i] = make_float4(0.f, 0.f, 0.f, 0.f);
    }

    // --- rank / srt (stable argsort) while the gather is in flight ---
    int ro = 0;
    if (t < NL) {
        const int tl = s_tim[t];
        int r = 0;
#pragma unroll
        for (int i = 0; i < 13; i++) {
            int4 w = ((const int4*)s_tim)[i];
            int j = 4 * i;
            r += (w.x < tl) | ((w.x == tl) & (j     < t));
            r += (w.y < tl) | ((w.y == tl) & (j + 1 < t));
            r += (w.z < tl) | ((w.z == tl) & (j + 2 < t));
            r += (w.w < tl) | ((w.w == tl) & (j + 3 < t));
        }
        s_srt[r] = t;          // srt[r] = original index of rank-r time
        ro = NL - 1 - r;       // re_order
    }

    // --- score dots + time-enc dots, shfl-reduced over each 16-lane group ---
#pragma unroll
    for (int i = 0; i < 13; i++) {
        const int l = 4 * i + g;
        float d = v[i].x * dstc.x + v[i].y * dstc.y + v[i].z * dstc.z + v[i].w * dstc.w;
        float4 tv = (l < NL) ? __ldg(&te4[l * 16 + c]) : make_float4(0.f, 0.f, 0.f, 0.f);
        float s = tv.x * dstc.x + tv.y * dstc.y + tv.z * dstc.z + tv.w * dstc.w;
#pragma unroll
        for (int m = 1; m < 16; m <<= 1) {
            d += __shfl_xor_sync(0xffffffffu, d, m);
            s += __shfl_xor_sync(0xffffffffu, s, m);
        }
        if (c == 0 && l < NL) { s_dot[l] = d; s_S[l] = s; }
    }
    __syncthreads();

    // --- e, rank prior, g ---
    if (t < NL) {
        float e = (s_dot[t] + s_S[ro]) * 6.25f;           // L/sqrt(D)
        float p = expf((float)s_srt[t] - 49.0f) * INV_C;  // softmax of permutation
        s_g[t] = e * p;
    }
    __syncthreads();

    // --- softmax over g (redundant per-thread) ---
    float mx = -1e30f;
#pragma unroll
    for (int i = 0; i < 13; i++) {
        float4 g4 = ((const float4*)s_g)[i];
        mx = fmaxf(mx, fmaxf(fmaxf(g4.x, g4.y), fmaxf(g4.z, g4.w)));
    }
    if (t < NL) s_alpha[t] = expf(s_g[t] - mx);
    __syncthreads();
    float sum = 0.f;
#pragma unroll
    for (int i = 0; i < 13; i++) {
        float4 a4 = ((const float4*)s_alpha)[i];
        sum += a4.x + a4.y + a4.z + a4.w;
    }
    const float inv = 1.0f / sum;

    // --- weighted column sums in registers ---
    float4 pc = make_float4(0.f, 0.f, 0.f, 0.f);
#pragma unroll
    for (int i = 0; i < 13; i++) {
        const float a = s_alpha[4 * i + g];   // pad zeros kill l>=50 terms
        pc.x += a * v[i].x; pc.y += a * v[i].y;
        pc.z += a * v[i].z; pc.w += a * v[i].w;
    }
    // combine the two groups within each warp
    pc.x += __shfl_xor_sync(0xffffffffu, pc.x, 16);
    pc.y += __shfl_xor_sync(0xffffffffu, pc.y, 16);
    pc.z += __shfl_xor_sync(0xffffffffu, pc.z, 16);
    pc.w += __shfl_xor_sync(0xffffffffu, pc.w, 16);
    if ((t & 31) < 16) s_red[(t >> 5) * 16 + c] = pc;
    __syncthreads();

    // combine the two warps, scale, store
    if (t < 16) {
        float4 a = s_red[t], b = s_red[16 + t];
        float4 h;
        h.x = (a.x + b.x) * inv;
        h.y = (a.y + b.y) * inv;
        h.z = (a.z + b.z) * inv;
        h.w = (a.w + b.w) * inv;
        ((float4*)(g_H + (size_t)row * ND))[t] = h;
    }
}

// ------------------------------------------------------------------
// Kernel 2: out = relu(H @ W1 + b1) @ W2 + b2   (exact R0 version)
// ------------------------------------------------------------------
__global__ __launch_bounds__(128) void mlp_kernel(
    const float* __restrict__ W1u, const float* __restrict__ b1u,
    const float* __restrict__ W2u, const float* __restrict__ b2u,
    const float* __restrict__ W1i, const float* __restrict__ b1i,
    const float* __restrict__ W2i, const float* __restrict__ b2i,
    float* __restrict__ out)
{
    __shared__ __align__(16) float4 sW1[ND * 16];
    __shared__ __align__(16) float4 sW2[ND * 16];
    __shared__ __align__(16) float4 sb1[16];
    __shared__ __align__(16) float4 sb2[16];

    const int side = blockIdx.y;
    const float* W1 = side ? W1i : W1u;
    const float* W2 = side ? W2i : W2u;
    const float* b1 = side ? b1i : b1u;
    const float* b2 = side ? b2i : b2u;

    for (int i = threadIdx.x; i < ND * 16; i += 128) {
        sW1[i] = ((const float4*)W1)[i];
        sW2[i] = ((const float4*)W2)[i];
    }
    if (threadIdx.x < 16) {
        sb1[threadIdx.x] = ((const float4*)b1)[threadIdx.x];
        sb2[threadIdx.x] = ((const float4*)b2)[threadIdx.x];
    }
    __syncthreads();

    const int n = blockIdx.x * 128 + threadIdx.x;
    if (n >= NROWS) return;
    const size_t grow = (size_t)side * NROWS + n;

    float hreg[ND];
    const float4* Hrow = (const float4*)(g_H + grow * ND);
#pragma unroll
    for (int c = 0; c < 16; c++) ((float4*)hreg)[c] = Hrow[c];

    float4 o1[16];
#pragma unroll
    for (int c = 0; c < 16; c++) o1[c] = sb1[c];
#pragma unroll
    for (int k = 0; k < ND; k++) {
        float hk = hreg[k];
#pragma unroll
        for (int c = 0; c < 16; c++) {
            float4 w = sW1[k * 16 + c];
            o1[c].x += hk * w.x; o1[c].y += hk * w.y;
            o1[c].z += hk * w.z; o1[c].w += hk * w.w;
        }
    }
    float o1f[ND];
#pragma unroll
    for (int c = 0; c < 16; c++) {
        o1f[4 * c + 0] = fmaxf(o1[c].x, 0.f);
        o1f[4 * c + 1] = fmaxf(o1[c].y, 0.f);
        o1f[4 * c + 2] = fmaxf(o1[c].z, 0.f);
        o1f[4 * c + 3] = fmaxf(o1[c].w, 0.f);
    }

    float4 o2[16];
#pragma unroll
    for (int c = 0; c < 16; c++) o2[c] = sb2[c];
#pragma unroll
    for (int k = 0; k < ND; k++) {
        float hk = o1f[k];
#pragma unroll
        for (int c = 0; c < 16; c++) {
            float4 w = sW2[k * 16 + c];
            o2[c].x += hk * w.x; o2[c].y += hk * w.y;
            o2[c].z += hk * w.z; o2[c].w += hk * w.w;
        }
    }

    float4* orow = (float4*)(out + grow * ND);
#pragma unroll
    for (int c = 0; c < 16; c++) orow[c] = o2[c];
}

// ------------------------------------------------------------------
extern "C" void kernel_launch(void* const* d_in, const int* in_sizes, int n_in,
                              void* d_out, int out_size)
{
    const float* user_h = (const float*)d_in[0];
    const float* item_h = (const float*)d_in[1];
    const float* u_te   = (const float*)d_in[2];
    const float* i_te   = (const float*)d_in[3];
    const float* Wu1 = (const float*)d_in[4];
    const float* bu1 = (const float*)d_in[5];
    const float* Wu2 = (const float*)d_in[6];
    const float* bu2 = (const float*)d_in[7];
    const float* Wi1 = (const float*)d_in[8];
    const float* bi1 = (const float*)d_in[9];
    const float* Wi2 = (const float*)d_in[10];
    const float* bi2 = (const float*)d_in[11];
    const int* u_nbr = (const int*)d_in[12];
    const int* u_tim = (const int*)d_in[13];
    const int* i_nbr = (const int*)d_in[14];
    const int* i_tim = (const int*)d_in[15];
    float* out = (float*)d_out;

    attn_kernel<<<TOTROWS, 64>>>(user_h, item_h, u_te, i_te,
                                 u_nbr, u_tim, i_nbr, i_tim);
    mlp_kernel<<<dim3((NROWS + 127) / 128, 2), 128>>>(Wu1, bu1, Wu2, bu2,
                                                      Wi1, bi1, Wi2, bi2, out);
}

// round 4
// speedup vs baseline: 2.3889x; 1.2101x over previous
#include <cuda_runtime.h>
#include <cstdint>

#define NL 50
#define ND 64
#define NROWS 50000
#define TOTROWS 100000

// 1 / sum_{m=0}^{49} e^{-m}
#define INV_C 0.63212055882855767841f

__device__ float g_H[(size_t)TOTROWS * ND];   // attention output scratch (25.6 MB)

// ------------------------------------------------------------------
// Fused attention kernel: one 64-thread block per destination row.
// Neighbor tile in registers (13 float4/thread). Score dots reduced with
// 2 shfl levels (quad partials) + smem gather-sum.
// Thread t: group g = t>>4 (rows 4i+g), chunk c = t&15 (cols 4c..4c+3).
// ------------------------------------------------------------------
__global__ __launch_bounds__(64) void attn_kernel(
    const float* __restrict__ user_h, const float* __restrict__ item_h,
    const float* __restrict__ u_te,   const float* __restrict__ i_te,
    const int* __restrict__ u_nbr, const int* __restrict__ u_tim,
    const int* __restrict__ i_nbr, const int* __restrict__ i_tim)
{
    __shared__ __align__(16) int   s_tim[52];
    __shared__ __align__(16) int   s_idx[52];
    __shared__ __align__(16) int   s_srt[52];
    __shared__ __align__(16) float s_pd[NL * 4];   // quad partials of <nbr,dst>
    __shared__ __align__(16) float s_ps[NL * 4];   // quad partials of <te,dst>
    __shared__ __align__(16) float s_S[52];
    __shared__ __align__(16) float s_g[52];
    __shared__ __align__(16) float s_alpha[52];
    __shared__ __align__(16) float4 s_red[32];

    const int row = blockIdx.x;
    const int t = threadIdx.x;
    const int g = t >> 4, c = t & 15;
    const bool uside = row < NROWS;
    const int n = uside ? row : row - NROWS;
    const float*  dst  = (uside ? user_h : item_h) + (size_t)n * ND;
    const float4* src4 = (const float4*)(uside ? item_h : user_h);
    const float4* te4  = (const float4*)(uside ? u_te : i_te);
    const int* nbr = (uside ? u_nbr : i_nbr) + (size_t)n * NL;
    const int* tim = (uside ? u_tim : i_tim) + (size_t)n * NL;

    const float4 dstc = __ldg(&((const float4*)dst)[c]);

    if (t < NL) {
        s_idx[t] = __ldg(nbr + t);
        s_tim[t] = __ldg(tim + t);
    } else if (t < 52) {
        s_tim[t]   = 0x7fffffff;   // pad: strictly greater, no ties
        s_idx[t]   = 0;
        s_g[t]     = -1e30f;
        s_alpha[t] = 0.f;
    }
    __syncthreads();

    // --- gather: 16 consecutive lanes fetch one 256B neighbor row ---
    float4 v[13];
#pragma unroll
    for (int i = 0; i < 13; i++) {
        const int l = 4 * i + g;
        if (l < NL)
            v[i] = __ldg(&src4[(size_t)s_idx[l] * 16 + c]);
        else
            v[i] = make_float4(0.f, 0.f, 0.f, 0.f);
    }

    // --- rank / srt (stable argsort) while gather is in flight ---
    int ro = 0;
    if (t < NL) {
        const int tl = s_tim[t];
        int r = 0;
#pragma unroll
        for (int i = 0; i < 13; i++) {
            int4 w = ((const int4*)s_tim)[i];
            int j = 4 * i;
            r += (w.x < tl) | ((w.x == tl) & (j     < t));
            r += (w.y < tl) | ((w.y == tl) & (j + 1 < t));
            r += (w.z < tl) | ((w.z == tl) & (j + 2 < t));
            r += (w.w < tl) | ((w.w == tl) & (j + 3 < t));
        }
        s_srt[r] = t;
        ro = NL - 1 - r;
    }

    // --- score + te dots: 2 shfl levels -> quad partials -> smem ---
#pragma unroll
    for (int i = 0; i < 13; i++) {
        const int l = 4 * i + g;
        float d = v[i].x * dstc.x + v[i].y * dstc.y + v[i].z * dstc.z + v[i].w * dstc.w;
        float4 tv = (l < NL) ? __ldg(&te4[l * 16 + c]) : make_float4(0.f, 0.f, 0.f, 0.f);
        float s = tv.x * dstc.x + tv.y * dstc.y + tv.z * dstc.z + tv.w * dstc.w;
        d += __shfl_xor_sync(0xffffffffu, d, 1);
        d += __shfl_xor_sync(0xffffffffu, d, 2);
        s += __shfl_xor_sync(0xffffffffu, s, 1);
        s += __shfl_xor_sync(0xffffffffu, s, 2);
        if (((c & 3) == 0) && l < NL) {
            s_pd[l * 4 + (c >> 2)] = d;
            s_ps[l * 4 + (c >> 2)] = s;
        }
    }
    __syncthreads();   // partials + s_srt visible

    // --- finish the reductions ---
    float dsum = 0.f;
    if (t < NL) {
        float4 pd = ((const float4*)s_pd)[t];
        float4 ps = ((const float4*)s_ps)[t];
        dsum = pd.x + pd.y + pd.z + pd.w;
        s_S[t] = ps.x + ps.y + ps.z + ps.w;
    }
    __syncthreads();   // s_S visible

    // --- e, rank prior, g ---
    if (t < NL) {
        float e = (dsum + s_S[ro]) * 6.25f;               // L/sqrt(D)
        float p = expf((float)s_srt[t] - 49.0f) * INV_C;  // softmax of permutation
        s_g[t] = e * p;
    }
    __syncthreads();

    // --- softmax over g (redundant per-thread) ---
    float mx = -1e30f;
#pragma unroll
    for (int i = 0; i < 13; i++) {
        float4 g4 = ((const float4*)s_g)[i];
        mx = fmaxf(mx, fmaxf(fmaxf(g4.x, g4.y), fmaxf(g4.z, g4.w)));
    }
    if (t < NL) s_alpha[t] = expf(s_g[t] - mx);
    __syncthreads();
    float sum = 0.f;
#pragma unroll
    for (int i = 0; i < 13; i++) {
        float4 a4 = ((const float4*)s_alpha)[i];
        sum += a4.x + a4.y + a4.z + a4.w;
    }
    const float inv = 1.0f / sum;

    // --- weighted column sums in registers ---
    float4 pc = make_float4(0.f, 0.f, 0.f, 0.f);
#pragma unroll
    for (int i = 0; i < 13; i++) {
        const float a = s_alpha[4 * i + g];   // pad zeros kill l>=50
        pc.x += a * v[i].x; pc.y += a * v[i].y;
        pc.z += a * v[i].z; pc.w += a * v[i].w;
    }
    pc.x += __shfl_xor_sync(0xffffffffu, pc.x, 16);
    pc.y += __shfl_xor_sync(0xffffffffu, pc.y, 16);
    pc.z += __shfl_xor_sync(0xffffffffu, pc.z, 16);
    pc.w += __shfl_xor_sync(0xffffffffu, pc.w, 16);
    if ((t & 31) < 16) s_red[(t >> 5) * 16 + c] = pc;
    __syncthreads();

    if (t < 16) {
        float4 a = s_red[t], b = s_red[16 + t];
        float4 h;
        h.x = (a.x + b.x) * inv;
        h.y = (a.y + b.y) * inv;
        h.z = (a.z + b.z) * inv;
        h.w = (a.w + b.w) * inv;
        ((float4*)(g_H + (size_t)row * ND))[t] = h;
    }
}

// ------------------------------------------------------------------
// Kernel 2: out = relu(H @ W1 + b1) @ W2 + b2
// 128 rows per block; H staged k-major in smem (stride 129); layer
// boundary through each thread's private smem column; f32x2 packed FMA.
// ------------------------------------------------------------------
#define HTS 129

__global__ __launch_bounds__(128) void mlp_kernel(
    const float* __restrict__ W1u, const float* __restrict__ b1u,
    const float* __restrict__ W2u, const float* __restrict__ b2u,
    const float* __restrict__ W1i, const float* __restrict__ b1i,
    const float* __restrict__ W2i, const float* __restrict__ b2i,
    float* __restrict__ out)
{
    __shared__ __align__(16) float4 sW1[ND * 16];   // 16 KB
    __shared__ __align__(16) float4 sW2[ND * 16];   // 16 KB
    __shared__ float sb1[ND];
    __shared__ float sb2[ND];
    __shared__ __align__(16) float sHT[ND * HTS];   // 33 KB, k-major

    const int side = blockIdx.y;
    const float* W1 = side ? W1i : W1u;
    const float* W2 = side ? W2i : W2u;
    const float* b1 = side ? b1i : b1u;
    const float* b2 = side ? b2i : b2u;
    const int t = threadIdx.x;

    for (int i = t; i < ND * 16; i += 128) {
        sW1[i] = ((const float4*)W1)[i];
        sW2[i] = ((const float4*)W2)[i];
    }
    if (t < ND) { sb1[t] = b1[t]; sb2[t] = b2[t]; }

    const int base = blockIdx.x * 128;
    const int rows = min(128, NROWS - base);
    const float* Hbase = g_H + ((size_t)side * NROWS + base) * ND;

    // load H tile transposed (coalesced gmem, conflict-free smem)
    for (int i = 0; i < 64; i++) {
        int e = i * 128 + t;
        int r = e >> 6, k = e & 63;
        sHT[k * HTS + r] = (r < rows) ? Hbase[e] : 0.f;
    }
    __syncthreads();

    const int r = t;
    const ulonglong2* W1p = (const ulonglong2*)sW1;
    const ulonglong2* W2p = (const ulonglong2*)sW2;

    // ---- layer 1 ----
    unsigned long long acc[32];
#pragma unroll
    for (int j = 0; j < 32; j++)
        asm("mov.b64 %0, {%1, %2};" : "=l"(acc[j]) : "f"(sb1[2 * j]), "f"(sb1[2 * j + 1]));
#pragma unroll 4
    for (int k = 0; k < ND; k++) {
        float hk = sHT[k * HTS + r];
        unsigned long long hk2;
        asm("mov.b64 %0, {%1, %1};" : "=l"(hk2) : "f"(hk));
#pragma unroll
        for (int j = 0; j < 16; j++) {
            ulonglong2 w = W1p[k * 16 + j];
            asm("fma.rn.f32x2 %0, %1, %2, %0;" : "+l"(acc[2 * j])     : "l"(hk2), "l"(w.x));
            asm("fma.rn.f32x2 %0, %1, %2, %0;" : "+l"(acc[2 * j + 1]) : "l"(hk2), "l"(w.y));
        }
    }
    // relu -> own smem column (no cross-thread access, no sync needed)
#pragma unroll
    for (int j = 0; j < 32; j++) {
        float lo, hi;
        asm("mov.b64 {%0, %1}, %2;" : "=f"(lo), "=f"(hi) : "l"(acc[j]));
        sHT[(2 * j) * HTS + r]     = fmaxf(lo, 0.f);
        sHT[(2 * j + 1) * HTS + r] = fmaxf(hi, 0.f);
    }

    // ---- layer 2 ----
#pragma unroll
    for (int j = 0; j < 32; j++)
        asm("mov.b64 %0, {%1, %2};" : "=l"(acc[j]) : "f"(sb2[2 * j]), "f"(sb2[2 * j + 1]));
#pragma unroll 4
    for (int k = 0; k < ND; k++) {
        float hk = sHT[k * HTS + r];
        unsigned long long hk2;
        asm("mov.b64 %0, {%1, %1};" : "=l"(hk2) : "f"(hk));
#pragma unroll
        for (int j = 0; j < 16; j++) {
            ulonglong2 w = W2p[k * 16 + j];
            asm("fma.rn.f32x2 %0, %1, %2, %0;" : "+l"(acc[2 * j])     : "l"(hk2), "l"(w.x));
            asm("fma.rn.f32x2 %0, %1, %2, %0;" : "+l"(acc[2 * j + 1]) : "l"(hk2), "l"(w.y));
        }
    }
    // write o2 to own column, then cooperative coalesced store
#pragma unroll
    for (int j = 0; j < 32; j++) {
        float lo, hi;
        asm("mov.b64 {%0, %1}, %2;" : "=f"(lo), "=f"(hi) : "l"(acc[j]));
        sHT[(2 * j) * HTS + r]     = lo;
        sHT[(2 * j + 1) * HTS + r] = hi;
    }
    __syncthreads();

    float* Obase = out + ((size_t)side * NROWS + base) * ND;
    for (int i = 0; i < 64; i++) {
        int e = i * 128 + t;
        int rr = e >> 6, k = e & 63;
        if (rr < rows) Obase[e] = sHT[k * HTS + rr];
    }
}

// ------------------------------------------------------------------
extern "C" void kernel_launch(void* const* d_in, const int* in_sizes, int n_in,
                              void* d_out, int out_size)
{
    const float* user_h = (const float*)d_in[0];
    const float* item_h = (const float*)d_in[1];
    const float* u_te   = (const float*)d_in[2];
    const float* i_te   = (const float*)d_in[3];
    const float* Wu1 = (const float*)d_in[4];
    const float* bu1 = (const float*)d_in[5];
    const float* Wu2 = (const float*)d_in[6];
    const float* bu2 = (const float*)d_in[7];
    const float* Wi1 = (const float*)d_in[8];
    const float* bi1 = (const float*)d_in[9];
    const float* Wi2 = (const float*)d_in[10];
    const float* bi2 = (const float*)d_in[11];
    const int* u_nbr = (const int*)d_in[12];
    const int* u_tim = (const int*)d_in[13];
    const int* i_nbr = (const int*)d_in[14];
    const int* i_tim = (const int*)d_in[15];
    float* out = (float*)d_out;

    attn_kernel<<<TOTROWS, 64>>>(user_h, item_h, u_te, i_te,
                                 u_nbr, u_tim, i_nbr, i_tim);
    mlp_kernel<<<dim3((NROWS + 127) / 128, 2), 128>>>(Wu1, bu1, Wu2, bu2,
                                                      Wi1, bi1, Wi2, bi2, out);
}